// round 16
// baseline (speedup 1.0000x reference)
#include <cuda_runtime.h>
#include <cuda_bf16.h>
#include <cstddef>

#define N 4096
#define N4 (N / 4)
#define ROWS_PER_BLK 8
#define CBLK4 256          // float4-columns per block (256 threads)
#define SOLVE_BLKS (N / 4)     // 1024
#define BIGJ_BLKS  (N4 / CBLK4 * (N / ROWS_PER_BLK))  // 4*512 = 2048
#define TK1 2048               // T-rows carried by phase 1
#define TK2 (N - TK1)          // T-rows carried by phase 2

// ---------------- device scratch (no allocations allowed) ----------------
__device__ __align__(16) float4 g_col[N];  // per-column: {decay, P, Q, unused}
__device__ float  g_actX[N];
__device__ float  g_Bn[N];
__device__ float  g_diag[N];

// ---------------- T-row streamer (shared by both phases) -------------------
__device__ __forceinline__ void t_row_body(const float* __restrict__ Tt,
                                           float* __restrict__ outT,
                                           const int* __restrict__ prev,
                                           const int* __restrict__ curr,
                                           int row) {
    float prevb = (prev[row] > 0) ? 1.0f : 0.0f;
    const float4* T4 = reinterpret_cast<const float4*>(Tt + (size_t)row * N);
    float4*       O4 = reinterpret_cast<float4*>(outT + (size_t)row * N);
    const int4*   c4 = reinterpret_cast<const int4*>(curr);
#pragma unroll
    for (int k = 0; k < 4; k++) {
        int q = threadIdx.x + (k << 8);
        float4 tv = __ldcs(T4 + q);
        int4 cv = c4[q];
        float4 o;
        o.x = 0.99f * tv.x + (cv.x > 0 ? prevb : 0.0f);
        o.y = 0.99f * tv.y + (cv.y > 0 ? prevb : 0.0f);
        o.z = 0.99f * tv.z + (cv.z > 0 ? prevb : 0.0f);
        o.w = 0.99f * tv.w + (cv.w > 0 ? prevb : 0.0f);
        __stcs(O4 + q, o);
    }
}

// ---------------- phase 1: solve rows + first TK1 T-rows, one grid ---------
// Solve (blocks 0..1023): one J read total, 2 warps per row (split-K):
//   a1[i] = u[i] + 0.5*(J u)_i ; r1[i] = (J 1)_i
// Analytic deflation (1^T J = 1^T): act = a1 + 0.5*(S/N)*r1, S block-local.
// T blocks (1024..) are independent and soak the DRAM bandwidth the
// latency-bound solve leaves idle — guaranteed co-scheduled (same grid).
__global__ void k_phase1(const float* __restrict__ J, const float* __restrict__ x,
                         const float* __restrict__ Bpos, const float* __restrict__ Bneg,
                         const float* __restrict__ etainv, const float* __restrict__ Tcnt,
                         const int* __restrict__ prev, const int* __restrict__ curr,
                         const float* __restrict__ Tt, float* __restrict__ outT,
                         float* __restrict__ out_act, float* __restrict__ out_Bpos,
                         float* __restrict__ out_Bneg, float* __restrict__ out_eta,
                         float* __restrict__ out_Tcnt) {
    if (blockIdx.x >= SOLVE_BLKS) {
        t_row_body(Tt, outT, prev, curr, blockIdx.x - SOLVE_BLKS);
        return;
    }

    int warp = threadIdx.x >> 5;
    int lane = threadIdx.x & 31;
    int rowInBlk = warp >> 1;
    int half = warp & 1;
    int row = blockIdx.x * 4 + rowInBlk;

    const float4* Jr = reinterpret_cast<const float4*>(J + (size_t)row * N) + (half << 9);
    const float4* x4 = reinterpret_cast<const float4*>(x) + (half << 9);
    bool sum_warp = (rowInBlk == 0);   // warps 0,1 cover the full x between them

    float sx = 0.0f, sr = 0.0f, si = 0.0f;
#pragma unroll
    for (int k = 0; k < 16; k++) {
        int idx = lane + (k << 5);
        float4 jv = Jr[idx];
        float4 xv = x4[idx];
        sx += jv.x * xv.x + jv.y * xv.y + jv.z * xv.z + jv.w * xv.w;
        sr += jv.x + jv.y + jv.z + jv.w;
        if (sum_warp) si += xv.x + xv.y + xv.z + xv.w;
    }
#pragma unroll
    for (int off = 16; off > 0; off >>= 1) {
        sx += __shfl_down_sync(0xffffffffu, sx, off);
        sr += __shfl_down_sync(0xffffffffu, sr, off);
        if (sum_warp) si += __shfl_down_sync(0xffffffffu, si, off);
    }

    __shared__ float sxp[8], srp[8], sip[2];
    if (lane == 0) {
        sxp[warp] = sx;
        srp[warp] = sr;
        if (sum_warp) sip[half] = si;
    }
    __syncthreads();

    int t = threadIdx.x;
    if (t >= 4) return;
    int i = blockIdx.x * 4 + t;

    float a  = x[i] + 0.5f * (sxp[2 * t] + sxp[2 * t + 1]);
    float rv = srp[2 * t] + srp[2 * t + 1];
    float S  = sip[0] + sip[1];

    // analytic deflation: act = a1 + 0.5*(S/N)*r1  (=> sum(act) = 2S exactly)
    float act = a + 0.5f * S * (1.0f / (float)N) * rv;
    out_act[i] = act;

    float X = fminf(fmaxf(act, 0.0f), 1.0f);
    float act01 = (X >= 0.99f) ? 1.0f : 0.0f;

    const float lrp = (float)(0.1 / 0.12);
    float Bp = fminf((1.0f - lrp) * Bpos[i] + lrp * 7.0f * act01, 6.0f);
    float Bn = 0.9f * Bneg[i];  // A_NEG = 0, lr_n = 0.1

    float ei = (float)prev[i] + 0.99f * etainv[i];
    out_Bpos[i] = Bp;
    out_Bneg[i] = Bn;
    out_eta[i]  = ei;

    float prevb = (prev[i] > 0) ? 1.0f : 0.0f;
    out_Tcnt[i] = 0.99f * Tcnt[i] + prevb;

    float actX = (X < 0.99f) ? 0.0f : X;
    float Bpe = (Bp < 0.0f) ? 0.0f : Bp;   // UPDATE_MIN = 0
    float Bne = (Bn < 0.0f) ? 0.0f : Bn;
    float eta = 1.0f / ei;
    bool updated = (prev[i] == 1);

    float decay = updated ? (1.0f - eta) : 1.0f;
    float P = updated ? 1.008f * eta * Bpe : 0.0f;    // 0.1 * 10.08
    float Q = updated ? 1.008f * eta * actX : 0.0f;
    g_col[i] = make_float4(decay, P, Q, 0.0f);
    g_actX[i] = actX;
    g_Bn[i] = Bne;
    g_diag[i] = updated ? eta * 0.165f * actX * Bpe : 0.0f;  // 0.1 * 1.65
}

// ---------------- phase 2: bigJ tiles + remaining T-rows, one grid ---------
// bigJ (blocks 0..2047): column-stationary, coeffs in registers, 8 rows'
// J values front-batched via __ldcg. T blocks (2048..) soak the DRAM slack
// bigJ leaves (it ran only ~5.8 TB/s alone).
__global__ void k_phase2(const float* __restrict__ J, float* __restrict__ outJ,
                         const float* __restrict__ Tt, float* __restrict__ outT,
                         const int* __restrict__ prev, const int* __restrict__ curr) {
    int b = blockIdx.x;
    if (b >= BIGJ_BLKS) {
        t_row_body(Tt, outT, prev, curr, TK1 + (b - BIGJ_BLKS));
        return;
    }

    int q = (b & 3) * CBLK4 + threadIdx.x;   // this thread's float4 column
    int r0 = (b >> 2) * ROWS_PER_BLK;

    __shared__ float s_actX[ROWS_PER_BLK], s_Bn[ROWS_PER_BLK], s_diag[ROWS_PER_BLK];
    if (threadIdx.x < 3 * ROWS_PER_BLK) {
        int t = threadIdx.x;
        int sel = t >> 3;
        int rr = t & 7;
        if (sel == 0)      s_actX[rr] = g_actX[r0 + rr];
        else if (sel == 1) s_Bn[rr]   = g_Bn[r0 + rr];
        else               s_diag[rr] = g_diag[r0 + rr];
    }
    __syncthreads();

    int j0 = q << 2;
    float4 c0 = g_col[j0 + 0];
    float4 c1 = g_col[j0 + 1];
    float4 c2 = g_col[j0 + 2];
    float4 c3 = g_col[j0 + 3];

    const float4* J4 = reinterpret_cast<const float4*>(J);
    float4* oJ = reinterpret_cast<float4*>(outJ);
    size_t base = (size_t)r0 * N4 + q;

    // ---- front-batched loads: 8 independent LDG.128 in flight ----
    float4 jv[ROWS_PER_BLK];
#pragma unroll
    for (int rr = 0; rr < ROWS_PER_BLK; rr++)
        jv[rr] = __ldcg(J4 + base + (size_t)rr * N4);

#pragma unroll
    for (int rr = 0; rr < ROWS_PER_BLK; rr++) {
        int i = r0 + rr;
        float actXi = s_actX[rr];
        float Bni   = s_Bn[rr];

        float4 rj;
        rj.x = fminf(fmaxf(c0.x * jv[rr].x + actXi * c0.y + Bni * c0.z, 0.0f), 1.0f);
        rj.y = fminf(fmaxf(c1.x * jv[rr].y + actXi * c1.y + Bni * c1.z, 0.0f), 1.0f);
        rj.z = fminf(fmaxf(c2.x * jv[rr].z + actXi * c2.y + Bni * c2.z, 0.0f), 1.0f);
        rj.w = fminf(fmaxf(c3.x * jv[rr].w + actXi * c3.y + Bni * c3.z, 0.0f), 1.0f);

        if ((i >> 2) == q) {  // diagonal element lives in this thread's float4
            int c = i & 3;
            float Jx = (&jv[rr].x)[c];
            float dec = (c == 0) ? c0.x : (c == 1) ? c1.x : (c == 2) ? c2.x : c3.x;
            (&rj.x)[c] = fminf(fmaxf(dec * Jx + s_diag[rr], 0.0f), 1.0f);
        }
        __stcs(oJ + base + (size_t)rr * N4, rj);
    }
}

// ---------------- host launcher ----------------
extern "C" void kernel_launch(void* const* d_in, const int* in_sizes, int n_in,
                              void* d_out, int out_size) {
    const float* input  = (const float*)d_in[0];
    const float* J      = (const float*)d_in[1];
    const float* Bpos   = (const float*)d_in[2];
    const float* Bneg   = (const float*)d_in[3];
    const float* etainv = (const float*)d_in[4];
    const float* Tt     = (const float*)d_in[5];
    const float* Tcnt   = (const float*)d_in[6];
    const int*   prev   = (const int*)d_in[7];
    const int*   curr   = (const int*)d_in[8];

    float* out = (float*)d_out;
    float* out_act  = out;                         // N
    float* out_J    = out + N;                     // N*N
    float* out_Bpos = out_J + (size_t)N * N;       // N
    float* out_Bneg = out_Bpos + N;                // N
    float* out_eta  = out_Bneg + N;                // N
    float* out_Tt   = out_eta + N;                 // N*N
    float* out_Tcnt = out_Tt + (size_t)N * N;      // N

    // phase 1: solve (1024 blocks) + first 2048 T-rows, one grid
    k_phase1<<<SOLVE_BLKS + TK1, 256>>>(J, input, Bpos, Bneg, etainv, Tcnt,
                                        prev, curr, Tt, out_Tt,
                                        out_act, out_Bpos, out_Bneg, out_eta,
                                        out_Tcnt);

    // phase 2: bigJ (2048 blocks) + remaining 2048 T-rows, one grid
    k_phase2<<<BIGJ_BLKS + TK2, 256>>>(J, out_J, Tt, out_Tt, prev, curr);
}

// round 17
// speedup vs baseline: 1.0331x; 1.0331x over previous
#include <cuda_runtime.h>
#include <cuda_bf16.h>
#include <cstddef>

#define N 4096
#define N4 (N / 4)
#define ROWS_PER_BLK 8
#define CBLK4 256          // float4-columns per block (256 threads)

// ---------------- device scratch (no allocations allowed) ----------------
__device__ __align__(16) float4 g_col[N];  // per-column: {decay, P, Q, unused}
__device__ float  g_actX[N];
__device__ float  g_Bn[N];
__device__ float  g_diag[N];

// ---------------- side stream + fork/join events (created ONCE) -----------
struct HxSideStream {
    cudaStream_t s2;
    cudaEvent_t  eFork, eJoin;
    HxSideStream() {
        cudaStreamCreateWithFlags(&s2, cudaStreamNonBlocking);
        cudaEventCreateWithFlags(&eFork, cudaEventDisableTiming);
        cudaEventCreateWithFlags(&eJoin, cudaEventDisableTiming);
    }
};
static HxSideStream hx;

// ---------------- single-pass solve + fused epilogue ----------------------
// One J read total. 4 warps per row (split-K quarter rows), 2 rows per
// 256-thread block, grid = N/2 = 2048 blocks -> 16384 warps in flight with
// 8-deep load chains each: ~2x the outstanding DRAM loads of the 2-warp
// shape, attacking the solve's latency-boundedness.
//   a1[i] = u[i] + 0.5*(J u)_i ; r1[i] = (J 1)_i
// Analytic deflation (1^T J = 1^T): act = a1 + 0.5*(S/N)*r1; S = sum(u) is
// block-local (warps 0-3 jointly read all of x).
__global__ void k_solve(const float* __restrict__ J, const float* __restrict__ x,
                        const float* __restrict__ Bpos, const float* __restrict__ Bneg,
                        const float* __restrict__ etainv, const float* __restrict__ Tcnt,
                        const int* __restrict__ prev, const int* __restrict__ curr,
                        float* __restrict__ out_act, float* __restrict__ out_Bpos,
                        float* __restrict__ out_Bneg, float* __restrict__ out_eta,
                        float* __restrict__ out_Tcnt) {
    int warp = threadIdx.x >> 5;
    int lane = threadIdx.x & 31;
    int rowInBlk = warp >> 2;          // 0..1
    int quarter  = warp & 3;           // 0..3
    int row = blockIdx.x * 2 + rowInBlk;

    const float4* Jr = reinterpret_cast<const float4*>(J + (size_t)row * N) + (quarter << 8);
    const float4* x4 = reinterpret_cast<const float4*>(x) + (quarter << 8);
    bool sum_warp = (rowInBlk == 0);   // warps 0-3 cover the full x between them

    float sx = 0.0f, sr = 0.0f, si = 0.0f;
#pragma unroll
    for (int k = 0; k < 8; k++) {
        int idx = lane + (k << 5);
        float4 jv = __ldcg(Jr + idx);   // single-use: skip L1
        float4 xv = x4[idx];
        sx += jv.x * xv.x + jv.y * xv.y + jv.z * xv.z + jv.w * xv.w;
        sr += jv.x + jv.y + jv.z + jv.w;
        if (sum_warp) si += xv.x + xv.y + xv.z + xv.w;
    }
#pragma unroll
    for (int off = 16; off > 0; off >>= 1) {
        sx += __shfl_down_sync(0xffffffffu, sx, off);
        sr += __shfl_down_sync(0xffffffffu, sr, off);
        if (sum_warp) si += __shfl_down_sync(0xffffffffu, si, off);
    }

    __shared__ float sxp[8], srp[8], sip[4];
    if (lane == 0) {
        sxp[warp] = sx;
        srp[warp] = sr;
        if (sum_warp) sip[quarter] = si;
    }
    __syncthreads();

    int t = threadIdx.x;
    if (t >= 2) return;
    int i = blockIdx.x * 2 + t;

    int w0 = 4 * t;
    float a  = x[i] + 0.5f * ((sxp[w0] + sxp[w0 + 1]) + (sxp[w0 + 2] + sxp[w0 + 3]));
    float rv = (srp[w0] + srp[w0 + 1]) + (srp[w0 + 2] + srp[w0 + 3]);
    float S  = (sip[0] + sip[1]) + (sip[2] + sip[3]);

    // analytic deflation: act = a1 + 0.5*(S/N)*r1  (=> sum(act) = 2S exactly)
    float act = a + 0.5f * S * (1.0f / (float)N) * rv;
    out_act[i] = act;

    float X = fminf(fmaxf(act, 0.0f), 1.0f);
    float act01 = (X >= 0.99f) ? 1.0f : 0.0f;

    const float lrp = (float)(0.1 / 0.12);
    float Bp = fminf((1.0f - lrp) * Bpos[i] + lrp * 7.0f * act01, 6.0f);
    float Bn = 0.9f * Bneg[i];  // A_NEG = 0, lr_n = 0.1

    float ei = (float)prev[i] + 0.99f * etainv[i];
    out_Bpos[i] = Bp;
    out_Bneg[i] = Bn;
    out_eta[i]  = ei;

    float prevb = (prev[i] > 0) ? 1.0f : 0.0f;
    out_Tcnt[i] = 0.99f * Tcnt[i] + prevb;

    float actX = (X < 0.99f) ? 0.0f : X;
    float Bpe = (Bp < 0.0f) ? 0.0f : Bp;   // UPDATE_MIN = 0
    float Bne = (Bn < 0.0f) ? 0.0f : Bn;
    float eta = 1.0f / ei;
    bool updated = (prev[i] == 1);

    float decay = updated ? (1.0f - eta) : 1.0f;
    float P = updated ? 1.008f * eta * Bpe : 0.0f;    // 0.1 * 10.08
    float Q = updated ? 1.008f * eta * actX : 0.0f;
    g_col[i] = make_float4(decay, P, Q, 0.0f);
    g_actX[i] = actX;
    g_Bn[i] = Bne;
    g_diag[i] = updated ? eta * 0.165f * actX * Bpe : 0.0f;  // 0.1 * 1.65
}

// ---------------- T branch: outT = 0.99*Tt + prevb_i * currb_j -------------
// Depends ONLY on raw inputs -> side stream, concurrent with solve + bigJ.
__global__ void k_bigT(const float* __restrict__ Tt, float* __restrict__ outT,
                       const int* __restrict__ prev, const int* __restrict__ curr) {
    int i = blockIdx.x;
    float prevb = (prev[i] > 0) ? 1.0f : 0.0f;
    const float4* T4 = reinterpret_cast<const float4*>(Tt + (size_t)i * N);
    float4*       O4 = reinterpret_cast<float4*>(outT + (size_t)i * N);
    const int4*   c4 = reinterpret_cast<const int4*>(curr);
#pragma unroll
    for (int k = 0; k < 4; k++) {
        int q = threadIdx.x + (k << 8);
        float4 tv = __ldcs(T4 + q);
        int4 cv = c4[q];
        float4 o;
        o.x = 0.99f * tv.x + (cv.x > 0 ? prevb : 0.0f);
        o.y = 0.99f * tv.y + (cv.y > 0 ? prevb : 0.0f);
        o.z = 0.99f * tv.z + (cv.z > 0 ? prevb : 0.0f);
        o.w = 0.99f * tv.w + (cv.w > 0 ? prevb : 0.0f);
        __stcs(O4 + q, o);
    }
}

// ---------------- J branch: column-stationary + front-batched loads --------
__global__ void k_bigJ(const float* __restrict__ J, float* __restrict__ outJ) {
    int q = blockIdx.x * CBLK4 + threadIdx.x;   // this thread's float4 column
    int r0 = blockIdx.y * ROWS_PER_BLK;

    __shared__ float s_actX[ROWS_PER_BLK], s_Bn[ROWS_PER_BLK], s_diag[ROWS_PER_BLK];
    if (threadIdx.x < 3 * ROWS_PER_BLK) {
        int t = threadIdx.x;
        int sel = t >> 3;
        int rr = t & 7;
        if (sel == 0)      s_actX[rr] = g_actX[r0 + rr];
        else if (sel == 1) s_Bn[rr]   = g_Bn[r0 + rr];
        else               s_diag[rr] = g_diag[r0 + rr];
    }
    __syncthreads();

    int j0 = q << 2;
    float4 c0 = g_col[j0 + 0];
    float4 c1 = g_col[j0 + 1];
    float4 c2 = g_col[j0 + 2];
    float4 c3 = g_col[j0 + 3];

    const float4* J4 = reinterpret_cast<const float4*>(J);
    float4* oJ = reinterpret_cast<float4*>(outJ);
    size_t base = (size_t)r0 * N4 + q;

    // ---- front-batched loads: 8 independent LDG.128 in flight ----
    float4 jv[ROWS_PER_BLK];
#pragma unroll
    for (int rr = 0; rr < ROWS_PER_BLK; rr++)
        jv[rr] = __ldcg(J4 + base + (size_t)rr * N4);

#pragma unroll
    for (int rr = 0; rr < ROWS_PER_BLK; rr++) {
        int i = r0 + rr;
        float actXi = s_actX[rr];
        float Bni   = s_Bn[rr];

        float4 rj;
        rj.x = fminf(fmaxf(c0.x * jv[rr].x + actXi * c0.y + Bni * c0.z, 0.0f), 1.0f);
        rj.y = fminf(fmaxf(c1.x * jv[rr].y + actXi * c1.y + Bni * c1.z, 0.0f), 1.0f);
        rj.z = fminf(fmaxf(c2.x * jv[rr].z + actXi * c2.y + Bni * c2.z, 0.0f), 1.0f);
        rj.w = fminf(fmaxf(c3.x * jv[rr].w + actXi * c3.y + Bni * c3.z, 0.0f), 1.0f);

        if ((i >> 2) == q) {  // diagonal element lives in this thread's float4
            int c = i & 3;
            float Jx = (&jv[rr].x)[c];
            float dec = (c == 0) ? c0.x : (c == 1) ? c1.x : (c == 2) ? c2.x : c3.x;
            (&rj.x)[c] = fminf(fmaxf(dec * Jx + s_diag[rr], 0.0f), 1.0f);
        }
        __stcs(oJ + base + (size_t)rr * N4, rj);
    }
}

// ---------------- host launcher ----------------
extern "C" void kernel_launch(void* const* d_in, const int* in_sizes, int n_in,
                              void* d_out, int out_size) {
    const float* input  = (const float*)d_in[0];
    const float* J      = (const float*)d_in[1];
    const float* Bpos   = (const float*)d_in[2];
    const float* Bneg   = (const float*)d_in[3];
    const float* etainv = (const float*)d_in[4];
    const float* Tt     = (const float*)d_in[5];
    const float* Tcnt   = (const float*)d_in[6];
    const int*   prev   = (const int*)d_in[7];
    const int*   curr   = (const int*)d_in[8];

    float* out = (float*)d_out;
    float* out_act  = out;                         // N
    float* out_J    = out + N;                     // N*N
    float* out_Bpos = out_J + (size_t)N * N;       // N
    float* out_Bneg = out_Bpos + N;                // N
    float* out_eta  = out_Bneg + N;                // N
    float* out_Tt   = out_eta + N;                 // N*N
    float* out_Tcnt = out_Tt + (size_t)N * N;      // N

    // ---- fork: T branch runs concurrently with the entire main chain ----
    cudaEventRecord(hx.eFork, 0);
    cudaStreamWaitEvent(hx.s2, hx.eFork, 0);
    k_bigT<<<N, 256, 0, hx.s2>>>(Tt, out_Tt, prev, curr);
    cudaEventRecord(hx.eJoin, hx.s2);

    // ---- main branch: single solve pass (fused epilogue) + J update ----
    k_solve<<<N / 2, 256>>>(J, input, Bpos, Bneg, etainv, Tcnt, prev, curr,
                            out_act, out_Bpos, out_Bneg, out_eta, out_Tcnt);

    dim3 grid(N4 / CBLK4, N / ROWS_PER_BLK);   // (4, 512) = 2048 blocks
    k_bigJ<<<grid, CBLK4>>>(J, out_J);

    // ---- join: main stream waits for the T branch ----
    cudaStreamWaitEvent(0, hx.eJoin, 0);
}